// round 14
// baseline (speedup 1.0000x reference)
#include <cuda_runtime.h>
#include <cuda_bf16.h>
#include <cuda_fp16.h>

#define N_NODES 100000
#define D 128
#define E_EDGES 1600000
#define SCAN_BLOCKS ((N_NODES + 1023) / 1024)   // 98
#define FULL 0xffffffffu

// Scratch (device globals; no runtime allocation allowed)
__device__ __half g_hhA[N_NODES * D];  // message tables (dinv*H, fp16), ping
__device__ __half g_hhB[N_NODES * D];  // pong
__device__ float g_dinv[N_NODES];
__device__ int   g_cnt[N_NODES];
__device__ int   g_rowptr[N_NODES + 1];
__device__ int   g_cursor[N_NODES];
__device__ int   g_csr_src[E_EDGES];
__device__ int   g_bsum[SCAN_BLOCKS];
__device__ int   g_boff[SCAN_BLOCKS];
// Fragment-packed W (fp16 main only): [kc][n][tk] -> {bm0,bm1}
__device__ uint2 g_wpk1[8 * D * 4];
__device__ uint2 g_wpk2[8 * D * 4];
__device__ uint2 g_wpk3[8 * D * 4];

// Side stream + events for fork-join graph capture (host driver objects).
struct SideRes {
    cudaStream_t s;
    cudaEvent_t fork, dinv, csr;
    SideRes() {
        cudaStreamCreateWithFlags(&s, cudaStreamNonBlocking);
        cudaEventCreateWithFlags(&fork, cudaEventDisableTiming);
        cudaEventCreateWithFlags(&dinv, cudaEventDisableTiming);
        cudaEventCreateWithFlags(&csr,  cudaEventDisableTiming);
    }
};
static SideRes g_res;

// ---------------------------------------------------------------------------
// Helpers
// ---------------------------------------------------------------------------
__device__ __forceinline__ void split2h(float2 v, unsigned& m, unsigned& r) {
    __half2 hm = __floats2half2_rn(v.x, v.y);
    float2 back = __half22float2(hm);
    __half2 hr = __floats2half2_rn(v.x - back.x, v.y - back.y);
    m = *(unsigned*)&hm;
    r = *(unsigned*)&hr;
}

__device__ __forceinline__ void mma_f16(float* c, unsigned a0, unsigned a1,
                                        unsigned a2, unsigned a3,
                                        unsigned b0, unsigned b1) {
    asm volatile(
        "mma.sync.aligned.m16n8k16.row.col.f32.f16.f16.f32 "
        "{%0,%1,%2,%3}, {%4,%5,%6,%7}, {%8,%9}, {%0,%1,%2,%3};"
        : "+f"(c[0]), "+f"(c[1]), "+f"(c[2]), "+f"(c[3])
        : "r"(a0), "r"(a1), "r"(a2), "r"(a3), "r"(b0), "r"(b1));
}

__device__ __forceinline__ void add_row(float* acc, uint4 raw) {
    float2 q0 = __half22float2(*(__half2*)&raw.x);
    float2 q1 = __half22float2(*(__half2*)&raw.y);
    float2 q2 = __half22float2(*(__half2*)&raw.z);
    float2 q3 = __half22float2(*(__half2*)&raw.w);
    acc[0] += q0.x; acc[1] += q0.y; acc[2] += q1.x; acc[3] += q1.y;
    acc[4] += q2.x; acc[5] += q2.y; acc[6] += q3.x; acc[7] += q3.y;
}

// Full-warp gather for one node: lanes 0-15 = even neighbors, 16-31 = odd.
// On return, ALL lanes hold the combined sum (self + all neighbors) for the
// 16B segment indexed by (lane & 15).
__device__ __forceinline__ void gather_node(const uint4* __restrict__ Hv,
                                            int node, int lane, float* acc) {
    int half = lane >> 4;
    int l16  = lane & 15;

    if (half == 0) {
        uint4 raw = Hv[node * 16 + l16];
        float2 q0 = __half22float2(*(__half2*)&raw.x);
        float2 q1 = __half22float2(*(__half2*)&raw.y);
        float2 q2 = __half22float2(*(__half2*)&raw.z);
        float2 q3 = __half22float2(*(__half2*)&raw.w);
        acc[0] = q0.x; acc[1] = q0.y; acc[2] = q1.x; acc[3] = q1.y;
        acc[4] = q2.x; acc[5] = q2.y; acc[6] = q3.x; acc[7] = q3.y;
    } else {
#pragma unroll
        for (int q = 0; q < 8; ++q) acc[q] = 0.0f;
    }

    int j = g_rowptr[node];
    int end = g_rowptr[node + 1];
    while (j < end) {
        int take = end - j;
        if (take > 32) take = 32;
        int sidx = (lane < take) ? g_csr_src[j + lane] : 0;
#pragma unroll 4
        for (int t = 0; t < take; t += 2) {
            int tt = t + half;
            int safe = (tt < take) ? tt : t;
            int s = __shfl_sync(FULL, sidx, safe);
            if (tt < take) {
                uint4 raw = Hv[s * 16 + l16];
                add_row(acc, raw);
            }
        }
        j += take;
    }

    // combine halves: every lane ends with the full sum
#pragma unroll
    for (int q = 0; q < 8; ++q)
        acc[q] += __shfl_xor_sync(FULL, acc[q], 16);
}

// ---------------------------------------------------------------------------
// CSR build: histogram -> dinv -> parallel scan -> scatter (4 edges/thread)
// ---------------------------------------------------------------------------
__global__ void k_zero_cnt() {
    int i = blockIdx.x * blockDim.x + threadIdx.x;
    if (i < N_NODES) g_cnt[i] = 0;
}

__global__ void k_count(const int* __restrict__ ei) {
    int e4 = blockIdx.x * blockDim.x + threadIdx.x;
    if (e4 < E_EDGES / 4) {
        int4 d = ((const int4*)(ei + E_EDGES))[e4];
        atomicAdd(&g_cnt[d.x], 1);
        atomicAdd(&g_cnt[d.y], 1);
        atomicAdd(&g_cnt[d.z], 1);
        atomicAdd(&g_cnt[d.w], 1);
    }
}

__global__ void k_dinv() {
    int i = blockIdx.x * blockDim.x + threadIdx.x;
    if (i < N_NODES) g_dinv[i] = rsqrtf((float)g_cnt[i] + 1.0f);
}

__global__ void __launch_bounds__(1024) k_scan_a() {
    __shared__ int sm[1024];
    int t = threadIdx.x;
    int i = blockIdx.x * 1024 + t;
    int v = (i < N_NODES) ? g_cnt[i] : 0;
    sm[t] = v;
    __syncthreads();
#pragma unroll
    for (int off = 1; off < 1024; off <<= 1) {
        int u = (t >= off) ? sm[t - off] : 0;
        __syncthreads();
        sm[t] += u;
        __syncthreads();
    }
    if (i < N_NODES) g_rowptr[i] = sm[t] - v;
    if (t == 1023) g_bsum[blockIdx.x] = sm[1023];
}

__global__ void __launch_bounds__(128) k_scan_b() {
    __shared__ int sm[128];
    int t = threadIdx.x;
    int v = (t < SCAN_BLOCKS) ? g_bsum[t] : 0;
    sm[t] = v;
    __syncthreads();
#pragma unroll
    for (int off = 1; off < 128; off <<= 1) {
        int u = (t >= off) ? sm[t - off] : 0;
        __syncthreads();
        sm[t] += u;
        __syncthreads();
    }
    if (t < SCAN_BLOCKS) g_boff[t] = sm[t] - v;
}

__global__ void __launch_bounds__(1024) k_scan_c() {
    int i = blockIdx.x * 1024 + threadIdx.x;
    if (i < N_NODES) {
        int r = g_rowptr[i] + g_boff[blockIdx.x];
        g_rowptr[i] = r;
        g_cursor[i] = r;
    }
    if (i == 0) g_rowptr[N_NODES] = E_EDGES;
}

__global__ void k_scatter(const int* __restrict__ ei) {
    int e4 = blockIdx.x * blockDim.x + threadIdx.x;
    if (e4 < E_EDGES / 4) {
        int4 s = ((const int4*)ei)[e4];
        int4 d = ((const int4*)(ei + E_EDGES))[e4];
        g_csr_src[atomicAdd(&g_cursor[d.x], 1)] = s.x;
        g_csr_src[atomicAdd(&g_cursor[d.y], 1)] = s.y;
        g_csr_src[atomicAdd(&g_cursor[d.z], 1)] = s.z;
        g_csr_src[atomicAdd(&g_cursor[d.w], 1)] = s.w;
    }
}

// ---------------------------------------------------------------------------
// W prep: fp16 main-only, fragment-packed uint2 {bm0,bm1}, all 3 layers.
// ---------------------------------------------------------------------------
__global__ void k_wprep_all(const float* __restrict__ W1,
                            const float* __restrict__ W2,
                            const float* __restrict__ W3) {
    int t = blockIdx.x * 256 + threadIdx.x;
    if (t >= 3 * 8 * D * 4) return;
    int layer = t / (8 * D * 4);
    int idx   = t % (8 * D * 4);
    int kc = idx >> 9;
    int n  = (idx >> 2) & 127;
    int tk = idx & 3;
    int k0 = kc * 16 + tk * 2;
    int k1 = k0 + 8;

    const float* W = (layer == 0) ? W1 : (layer == 1) ? W2 : W3;
    __half2 m0 = __floats2half2_rn(W[k0 * D + n], W[(k0 + 1) * D + n]);
    __half2 m1 = __floats2half2_rn(W[k1 * D + n], W[(k1 + 1) * D + n]);
    uint2 p = make_uint2(*(unsigned*)&m0, *(unsigned*)&m1);
    if (layer == 0) g_wpk1[idx] = p;
    else if (layer == 1) g_wpk2[idx] = p;
    else g_wpk3[idx] = p;
}

// ---------------------------------------------------------------------------
// Layer-1 GEMM: A = fp16 main+residual of fp32 x (2 MMA terms), W fp16 main.
// 8 warps; warp tile 32x64; block M=128, full N=128. Writes g_hhA.
// ---------------------------------------------------------------------------
__global__ void __launch_bounds__(256)
k_gemm_l1(const float* __restrict__ X) {
    int tid  = threadIdx.x;
    int warp = tid >> 5, lane = tid & 31;
    int g  = lane >> 2;
    int tk = lane & 3;
    int m0 = blockIdx.x * 128 + (warp & 3) * 32;
    int n0 = (warp >> 2) * 64;

    float c[2][8][4];
#pragma unroll
    for (int t = 0; t < 2; ++t)
#pragma unroll
        for (int j = 0; j < 8; ++j)
#pragma unroll
            for (int q = 0; q < 4; ++q) c[t][j][q] = 0.0f;

#pragma unroll 1
    for (int kc = 0; kc < 8; ++kc) {
        int kb = kc * 16;

        unsigned am[2][4], ar[2][4];
#pragma unroll
        for (int t = 0; t < 2; ++t) {
            int r0 = m0 + t * 16 + g;
            int r1 = r0 + 8;
            float2 z = make_float2(0.f, 0.f);
            float2 x00 = (r0 < N_NODES) ? *(const float2*)&X[r0 * 128 + kb + tk * 2] : z;
            float2 x10 = (r1 < N_NODES) ? *(const float2*)&X[r1 * 128 + kb + tk * 2] : z;
            float2 x01 = (r0 < N_NODES) ? *(const float2*)&X[r0 * 128 + kb + 8 + tk * 2] : z;
            float2 x11 = (r1 < N_NODES) ? *(const float2*)&X[r1 * 128 + kb + 8 + tk * 2] : z;
            split2h(x00, am[t][0], ar[t][0]);
            split2h(x10, am[t][1], ar[t][1]);
            split2h(x01, am[t][2], ar[t][2]);
            split2h(x11, am[t][3], ar[t][3]);
        }

        unsigned bm[8][2];
#pragma unroll
        for (int j = 0; j < 8; ++j) {
            uint2 w = g_wpk1[((kc * 128 + n0 + j * 8 + g) << 2) + tk];
            bm[j][0] = w.x; bm[j][1] = w.y;
        }

#pragma unroll
        for (int t = 0; t < 2; ++t)
#pragma unroll
            for (int j = 0; j < 8; ++j) {
                mma_f16(c[t][j], am[t][0], am[t][1], am[t][2], am[t][3],
                        bm[j][0], bm[j][1]);
                mma_f16(c[t][j], ar[t][0], ar[t][1], ar[t][2], ar[t][3],
                        bm[j][0], bm[j][1]);
            }
    }

#pragma unroll
    for (int t = 0; t < 2; ++t) {
        int r0 = m0 + t * 16 + g;
        int r1 = r0 + 8;
        float dv0 = (r0 < N_NODES) ? g_dinv[r0] : 0.f;
        float dv1 = (r1 < N_NODES) ? g_dinv[r1] : 0.f;
#pragma unroll
        for (int j = 0; j < 8; ++j) {
            int col = n0 + j * 8 + tk * 2;
            if (r0 < N_NODES)
                *(__half2*)&g_hhA[r0 * 128 + col] =
                    __floats2half2_rn(dv0 * c[t][j][0], dv0 * c[t][j][1]);
            if (r1 < N_NODES)
                *(__half2*)&g_hhA[r1 * 128 + col] =
                    __floats2half2_rn(dv1 * c[t][j][2], dv1 * c[t][j][3]);
        }
    }
}

// ---------------------------------------------------------------------------
// FUSED agg + GEMM (layers 2 and 3). Block = 128 nodes, 256 threads.
// Phase 1: warp w aggregates nodes [m0+16w, m0+16w+16): gather from HHprev,
//          bias+relu, fp16 -> smem A tile (conflict-free 136-half stride).
// Phase 2: fp16 MMA from smem A x packed W -> dinv-scaled fp16 HHnext.
// ---------------------------------------------------------------------------
template <int LAYER>
__global__ void __launch_bounds__(256)
k_aggemm(const float* __restrict__ bias) {
    __shared__ __half As[128][136];

    const __half* HHp = (LAYER == 2) ? g_hhA : g_hhB;
    __half*       HHn = (LAYER == 2) ? g_hhB : g_hhA;
    const uint2*  Wp  = (LAYER == 2) ? g_wpk2 : g_wpk3;

    int tid  = threadIdx.x;
    int warp = tid >> 5, lane = tid & 31;
    int l16  = lane & 15;
    int m0   = blockIdx.x * 128;
    const uint4* Hv = (const uint4*)HHp;

    float4 bb0 = *(const float4*)&bias[l16 * 8];
    float4 bb1 = *(const float4*)&bias[l16 * 8 + 4];

    // ---- Phase 1: aggregate 16 nodes per warp ----
#pragma unroll 1
    for (int i = 0; i < 16; ++i) {
        int rl = warp * 16 + i;        // local row 0..127
        int node = m0 + rl;
        if (node < N_NODES) {
            float acc[8];
            gather_node(Hv, node, lane, acc);
            if (lane < 16) {
                float dv = g_dinv[node];
                float o0 = fmaxf(fmaf(dv, acc[0], bb0.x), 0.f);
                float o1 = fmaxf(fmaf(dv, acc[1], bb0.y), 0.f);
                float o2 = fmaxf(fmaf(dv, acc[2], bb0.z), 0.f);
                float o3 = fmaxf(fmaf(dv, acc[3], bb0.w), 0.f);
                float o4 = fmaxf(fmaf(dv, acc[4], bb1.x), 0.f);
                float o5 = fmaxf(fmaf(dv, acc[5], bb1.y), 0.f);
                float o6 = fmaxf(fmaf(dv, acc[6], bb1.z), 0.f);
                float o7 = fmaxf(fmaf(dv, acc[7], bb1.w), 0.f);
                *(__half2*)&As[rl][l16 * 8 + 0] = __floats2half2_rn(o0, o1);
                *(__half2*)&As[rl][l16 * 8 + 2] = __floats2half2_rn(o2, o3);
                *(__half2*)&As[rl][l16 * 8 + 4] = __floats2half2_rn(o4, o5);
                *(__half2*)&As[rl][l16 * 8 + 6] = __floats2half2_rn(o6, o7);
            }
        } else if (lane < 16) {
            __half2 z = __floats2half2_rn(0.f, 0.f);
            *(__half2*)&As[rl][l16 * 8 + 0] = z;
            *(__half2*)&As[rl][l16 * 8 + 2] = z;
            *(__half2*)&As[rl][l16 * 8 + 4] = z;
            *(__half2*)&As[rl][l16 * 8 + 6] = z;
        }
    }
    __syncthreads();

    // ---- Phase 2: GEMM from smem ----
    int g  = lane >> 2;
    int tk = lane & 3;
    int mw = (warp & 3) * 32;        // local row base
    int n0 = (warp >> 2) * 64;

    float c[2][8][4];
#pragma unroll
    for (int t = 0; t < 2; ++t)
#pragma unroll
        for (int j = 0; j < 8; ++j)
#pragma unroll
            for (int q = 0; q < 4; ++q) c[t][j][q] = 0.0f;

#pragma unroll 1
    for (int kc = 0; kc < 8; ++kc) {
        int kb = kc * 16;
        unsigned a[2][4];
#pragma unroll
        for (int t = 0; t < 2; ++t) {
            int r0 = mw + t * 16 + g;
            int r1 = r0 + 8;
            a[t][0] = *(unsigned*)&As[r0][kb + tk * 2];
            a[t][2] = *(unsigned*)&As[r0][kb + tk * 2 + 8];
            a[t][1] = *(unsigned*)&As[r1][kb + tk * 2];
            a[t][3] = *(unsigned*)&As[r1][kb + tk * 2 + 8];
        }

        unsigned bm[8][2];
#pragma unroll
        for (int j = 0; j < 8; ++j) {
            uint2 w = Wp[((kc * 128 + n0 + j * 8 + g) << 2) + tk];
            bm[j][0] = w.x; bm[j][1] = w.y;
        }

#pragma unroll
        for (int t = 0; t < 2; ++t)
#pragma unroll
            for (int j = 0; j < 8; ++j)
                mma_f16(c[t][j], a[t][0], a[t][1], a[t][2], a[t][3],
                        bm[j][0], bm[j][1]);
    }

#pragma unroll
    for (int t = 0; t < 2; ++t) {
        int r0 = m0 + mw + t * 16 + g;
        int r1 = r0 + 8;
        float dv0 = (r0 < N_NODES) ? g_dinv[r0] : 0.f;
        float dv1 = (r1 < N_NODES) ? g_dinv[r1] : 0.f;
#pragma unroll
        for (int j = 0; j < 8; ++j) {
            int col = n0 + j * 8 + tk * 2;
            if (r0 < N_NODES)
                *(__half2*)&HHn[r0 * 128 + col] =
                    __floats2half2_rn(dv0 * c[t][j][0], dv0 * c[t][j][1]);
            if (r1 < N_NODES)
                *(__half2*)&HHn[r1 * 128 + col] =
                    __floats2half2_rn(dv1 * c[t][j][2], dv1 * c[t][j][3]);
        }
    }
}

// ---------------------------------------------------------------------------
// Final aggregation (layer 3 output): full warp per node, fp32 out.
// ---------------------------------------------------------------------------
__global__ void __launch_bounds__(256)
k_agg_out(const float* __restrict__ b, float* __restrict__ OUT) {
    int node = blockIdx.x * 8 + (threadIdx.x >> 5);
    int lane = threadIdx.x & 31;
    if (node >= N_NODES) return;

    float acc[8];
    gather_node((const uint4*)g_hhA, node, lane, acc);

    if (lane < 16) {
        int l16 = lane;
        float dv = g_dinv[node];
        float4 bb0 = *(const float4*)&b[l16 * 8];
        float4 bb1 = *(const float4*)&b[l16 * 8 + 4];
        float4 o0, o1;
        o0.x = fmaxf(fmaf(dv, acc[0], bb0.x), 0.f);
        o0.y = fmaxf(fmaf(dv, acc[1], bb0.y), 0.f);
        o0.z = fmaxf(fmaf(dv, acc[2], bb0.z), 0.f);
        o0.w = fmaxf(fmaf(dv, acc[3], bb0.w), 0.f);
        o1.x = fmaxf(fmaf(dv, acc[4], bb1.x), 0.f);
        o1.y = fmaxf(fmaf(dv, acc[5], bb1.y), 0.f);
        o1.z = fmaxf(fmaf(dv, acc[6], bb1.z), 0.f);
        o1.w = fmaxf(fmaf(dv, acc[7], bb1.w), 0.f);
        ((float4*)OUT)[node * 32 + l16 * 2]     = o0;
        ((float4*)OUT)[node * 32 + l16 * 2 + 1] = o1;
    }
}

// ---------------------------------------------------------------------------
extern "C" void kernel_launch(void* const* d_in, const int* in_sizes, int n_in,
                              void* d_out, int out_size) {
    const float* x  = (const float*)d_in[0];
    const int*   ei = (const int*)d_in[1];
    const float* W1 = (const float*)d_in[2];
    const float* b1 = (const float*)d_in[3];
    const float* W2 = (const float*)d_in[4];
    const float* b2 = (const float*)d_in[5];
    const float* W3 = (const float*)d_in[6];
    const float* b3 = (const float*)d_in[7];
    float* out = (float*)d_out;

    cudaStream_t side = g_res.s;

    // Fork: side stream builds CSR (+dinv early), main does wprep + gemm_l1.
    cudaEventRecord(g_res.fork, 0);
    cudaStreamWaitEvent(side, g_res.fork, 0);

    k_zero_cnt<<<(N_NODES + 255) / 256, 256, 0, side>>>();
    k_count<<<(E_EDGES / 4 + 255) / 256, 256, 0, side>>>(ei);
    k_dinv<<<(N_NODES + 255) / 256, 256, 0, side>>>();
    cudaEventRecord(g_res.dinv, side);
    k_scan_a<<<SCAN_BLOCKS, 1024, 0, side>>>();
    k_scan_b<<<1, 128, 0, side>>>();
    k_scan_c<<<SCAN_BLOCKS, 1024, 0, side>>>();
    k_scatter<<<(E_EDGES / 4 + 255) / 256, 256, 0, side>>>(ei);
    cudaEventRecord(g_res.csr, side);

    const int gemm_blocks = (N_NODES + 127) / 128;          // 782
    const int aggo_blocks = (N_NODES + 7) / 8;              // 12500

    k_wprep_all<<<(3 * 8 * D * 4 + 255) / 256, 256>>>(W1, W2, W3);
    cudaStreamWaitEvent(0, g_res.dinv, 0);
    k_gemm_l1<<<gemm_blocks, 256>>>(x);                     // x -> hhA
    cudaStreamWaitEvent(0, g_res.csr, 0);                   // join before gathers

    k_aggemm<2><<<gemm_blocks, 256>>>(b1);                  // hhA -> hhB
    k_aggemm<3><<<gemm_blocks, 256>>>(b2);                  // hhB -> hhA
    k_agg_out<<<aggo_blocks, 256>>>(b3, out);               // hhA -> out
}

// round 15
// speedup vs baseline: 1.3474x; 1.3474x over previous
#include <cuda_runtime.h>
#include <cuda_bf16.h>
#include <cuda_fp16.h>

#define N_NODES 100000
#define D 128
#define E_EDGES 1600000
#define SCAN_BLOCKS ((N_NODES + 1023) / 1024)   // 98
#define FULL 0xffffffffu

// Scratch (device globals; no runtime allocation allowed)
__device__ __half g_hh[N_NODES * D];   // pre-normalized messages dinv*H, fp16
__device__ __half g_act[N_NODES * D];  // activations, fp16, FRAGMENT-PERMUTED rows
__device__ float g_dinv[N_NODES];
__device__ int   g_cnt[N_NODES];
__device__ int   g_rowptr[N_NODES + 1];
__device__ int   g_cursor[N_NODES];
__device__ int   g_csr_src[E_EDGES];
__device__ int   g_bsum[SCAN_BLOCKS];
__device__ int   g_boff[SCAN_BLOCKS];
// Fragment-packed W (fp16 main only): [kc][n][tk] -> {bm0,bm1}
__device__ uint2 g_wpk1[8 * D * 4];
__device__ uint2 g_wpk2[8 * D * 4];
__device__ uint2 g_wpk3[8 * D * 4];

// Side stream + events for fork-join graph capture (host driver objects).
struct SideRes {
    cudaStream_t s;
    cudaEvent_t fork, dinv, csr;
    SideRes() {
        cudaStreamCreateWithFlags(&s, cudaStreamNonBlocking);
        cudaEventCreateWithFlags(&fork, cudaEventDisableTiming);
        cudaEventCreateWithFlags(&dinv, cudaEventDisableTiming);
        cudaEventCreateWithFlags(&csr,  cudaEventDisableTiming);
    }
};
static SideRes g_res;

// ---------------------------------------------------------------------------
// Helpers
// ---------------------------------------------------------------------------
__device__ __forceinline__ void split2h(float2 v, unsigned& m, unsigned& r) {
    __half2 hm = __floats2half2_rn(v.x, v.y);
    float2 back = __half22float2(hm);
    __half2 hr = __floats2half2_rn(v.x - back.x, v.y - back.y);
    m = *(unsigned*)&hm;
    r = *(unsigned*)&hr;
}

__device__ __forceinline__ void mma_f16(float* c, unsigned a0, unsigned a1,
                                        unsigned a2, unsigned a3,
                                        unsigned b0, unsigned b1) {
    asm volatile(
        "mma.sync.aligned.m16n8k16.row.col.f32.f16.f16.f32 "
        "{%0,%1,%2,%3}, {%4,%5,%6,%7}, {%8,%9}, {%0,%1,%2,%3};"
        : "+f"(c[0]), "+f"(c[1]), "+f"(c[2]), "+f"(c[3])
        : "r"(a0), "r"(a1), "r"(a2), "r"(a3), "r"(b0), "r"(b1));
}

__device__ __forceinline__ void add_row(float* acc, uint4 raw) {
    float2 q0 = __half22float2(*(__half2*)&raw.x);
    float2 q1 = __half22float2(*(__half2*)&raw.y);
    float2 q2 = __half22float2(*(__half2*)&raw.z);
    float2 q3 = __half22float2(*(__half2*)&raw.w);
    acc[0] += q0.x; acc[1] += q0.y; acc[2] += q1.x; acc[3] += q1.y;
    acc[4] += q2.x; acc[5] += q2.y; acc[6] += q3.x; acc[7] += q3.y;
}

// Full-warp gather for one node: lanes 0-15 = even neighbors, 16-31 = odd.
// On return, lanes 0-15 hold the combined sum (self + all neighbors) for the
// 16B segment indexed by (lane & 15).  (Proven correct in R14.)
__device__ __forceinline__ void gather_node(const uint4* __restrict__ Hv,
                                            int node, int lane, float* acc) {
    int half = lane >> 4;
    int l16  = lane & 15;

    if (half == 0) {
        uint4 raw = Hv[node * 16 + l16];
        float2 q0 = __half22float2(*(__half2*)&raw.x);
        float2 q1 = __half22float2(*(__half2*)&raw.y);
        float2 q2 = __half22float2(*(__half2*)&raw.z);
        float2 q3 = __half22float2(*(__half2*)&raw.w);
        acc[0] = q0.x; acc[1] = q0.y; acc[2] = q1.x; acc[3] = q1.y;
        acc[4] = q2.x; acc[5] = q2.y; acc[6] = q3.x; acc[7] = q3.y;
    } else {
#pragma unroll
        for (int q = 0; q < 8; ++q) acc[q] = 0.0f;
    }

    int j = g_rowptr[node];
    int end = g_rowptr[node + 1];
    while (j < end) {
        int take = end - j;
        if (take > 32) take = 32;
        int sidx = (lane < take) ? g_csr_src[j + lane] : 0;
#pragma unroll 4
        for (int t = 0; t < take; t += 2) {
            int tt = t + half;
            int safe = (tt < take) ? tt : t;
            int s = __shfl_sync(FULL, sidx, safe);
            if (tt < take) {
                uint4 raw = Hv[s * 16 + l16];
                add_row(acc, raw);
            }
        }
        j += take;
    }

#pragma unroll
    for (int q = 0; q < 8; ++q)
        acc[q] += __shfl_xor_sync(FULL, acc[q], 16);
}

// ---------------------------------------------------------------------------
// CSR build: histogram -> dinv -> parallel scan -> scatter (4 edges/thread)
// ---------------------------------------------------------------------------
__global__ void k_zero_cnt() {
    int i = blockIdx.x * blockDim.x + threadIdx.x;
    if (i < N_NODES) g_cnt[i] = 0;
}

__global__ void k_count(const int* __restrict__ ei) {
    int e4 = blockIdx.x * blockDim.x + threadIdx.x;
    if (e4 < E_EDGES / 4) {
        int4 d = ((const int4*)(ei + E_EDGES))[e4];
        atomicAdd(&g_cnt[d.x], 1);
        atomicAdd(&g_cnt[d.y], 1);
        atomicAdd(&g_cnt[d.z], 1);
        atomicAdd(&g_cnt[d.w], 1);
    }
}

__global__ void k_dinv() {
    int i = blockIdx.x * blockDim.x + threadIdx.x;
    if (i < N_NODES) g_dinv[i] = rsqrtf((float)g_cnt[i] + 1.0f);
}

__global__ void __launch_bounds__(1024) k_scan_a() {
    __shared__ int sm[1024];
    int t = threadIdx.x;
    int i = blockIdx.x * 1024 + t;
    int v = (i < N_NODES) ? g_cnt[i] : 0;
    sm[t] = v;
    __syncthreads();
#pragma unroll
    for (int off = 1; off < 1024; off <<= 1) {
        int u = (t >= off) ? sm[t - off] : 0;
        __syncthreads();
        sm[t] += u;
        __syncthreads();
    }
    if (i < N_NODES) g_rowptr[i] = sm[t] - v;
    if (t == 1023) g_bsum[blockIdx.x] = sm[1023];
}

__global__ void __launch_bounds__(128) k_scan_b() {
    __shared__ int sm[128];
    int t = threadIdx.x;
    int v = (t < SCAN_BLOCKS) ? g_bsum[t] : 0;
    sm[t] = v;
    __syncthreads();
#pragma unroll
    for (int off = 1; off < 128; off <<= 1) {
        int u = (t >= off) ? sm[t - off] : 0;
        __syncthreads();
        sm[t] += u;
        __syncthreads();
    }
    if (t < SCAN_BLOCKS) g_boff[t] = sm[t] - v;
}

__global__ void __launch_bounds__(1024) k_scan_c() {
    int i = blockIdx.x * 1024 + threadIdx.x;
    if (i < N_NODES) {
        int r = g_rowptr[i] + g_boff[blockIdx.x];
        g_rowptr[i] = r;
        g_cursor[i] = r;
    }
    if (i == 0) g_rowptr[N_NODES] = E_EDGES;
}

__global__ void k_scatter(const int* __restrict__ ei) {
    int e4 = blockIdx.x * blockDim.x + threadIdx.x;
    if (e4 < E_EDGES / 4) {
        int4 s = ((const int4*)ei)[e4];
        int4 d = ((const int4*)(ei + E_EDGES))[e4];
        g_csr_src[atomicAdd(&g_cursor[d.x], 1)] = s.x;
        g_csr_src[atomicAdd(&g_cursor[d.y], 1)] = s.y;
        g_csr_src[atomicAdd(&g_cursor[d.z], 1)] = s.z;
        g_csr_src[atomicAdd(&g_cursor[d.w], 1)] = s.w;
    }
}

// ---------------------------------------------------------------------------
// W prep: fp16 main-only, fragment-packed uint2 {bm0,bm1}, all 3 layers.
// ---------------------------------------------------------------------------
__global__ void k_wprep_all(const float* __restrict__ W1,
                            const float* __restrict__ W2,
                            const float* __restrict__ W3) {
    int t = blockIdx.x * 256 + threadIdx.x;
    if (t >= 3 * 8 * D * 4) return;
    int layer = t / (8 * D * 4);
    int idx   = t % (8 * D * 4);
    int kc = idx >> 9;
    int n  = (idx >> 2) & 127;
    int tk = idx & 3;
    int k0 = kc * 16 + tk * 2;
    int k1 = k0 + 8;

    const float* W = (layer == 0) ? W1 : (layer == 1) ? W2 : W3;
    __half2 m0 = __floats2half2_rn(W[k0 * D + n], W[(k0 + 1) * D + n]);
    __half2 m1 = __floats2half2_rn(W[k1 * D + n], W[(k1 + 1) * D + n]);
    uint2 p = make_uint2(*(unsigned*)&m0, *(unsigned*)&m1);
    if (layer == 0) g_wpk1[idx] = p;
    else if (layer == 1) g_wpk2[idx] = p;
    else g_wpk3[idx] = p;
}

// ---------------------------------------------------------------------------
// Layer-1 GEMM: A = fp16 main+residual of fp32 x (2 MMA terms), W fp16 main.
// 8 warps; warp tile 32x64; block M=128, full N=128. Writes g_hh.
// ---------------------------------------------------------------------------
__global__ void __launch_bounds__(256)
k_gemm_l1(const float* __restrict__ X) {
    int tid  = threadIdx.x;
    int warp = tid >> 5, lane = tid & 31;
    int g  = lane >> 2;
    int tk = lane & 3;
    int m0 = blockIdx.x * 128 + (warp & 3) * 32;
    int n0 = (warp >> 2) * 64;

    float c[2][8][4];
#pragma unroll
    for (int t = 0; t < 2; ++t)
#pragma unroll
        for (int j = 0; j < 8; ++j)
#pragma unroll
            for (int q = 0; q < 4; ++q) c[t][j][q] = 0.0f;

#pragma unroll 1
    for (int kc = 0; kc < 8; ++kc) {
        int kb = kc * 16;

        unsigned am[2][4], ar[2][4];
#pragma unroll
        for (int t = 0; t < 2; ++t) {
            int r0 = m0 + t * 16 + g;
            int r1 = r0 + 8;
            float2 z = make_float2(0.f, 0.f);
            float2 x00 = (r0 < N_NODES) ? *(const float2*)&X[r0 * 128 + kb + tk * 2] : z;
            float2 x10 = (r1 < N_NODES) ? *(const float2*)&X[r1 * 128 + kb + tk * 2] : z;
            float2 x01 = (r0 < N_NODES) ? *(const float2*)&X[r0 * 128 + kb + 8 + tk * 2] : z;
            float2 x11 = (r1 < N_NODES) ? *(const float2*)&X[r1 * 128 + kb + 8 + tk * 2] : z;
            split2h(x00, am[t][0], ar[t][0]);
            split2h(x10, am[t][1], ar[t][1]);
            split2h(x01, am[t][2], ar[t][2]);
            split2h(x11, am[t][3], ar[t][3]);
        }

        unsigned bm[8][2];
#pragma unroll
        for (int j = 0; j < 8; ++j) {
            uint2 w = g_wpk1[((kc * 128 + n0 + j * 8 + g) << 2) + tk];
            bm[j][0] = w.x; bm[j][1] = w.y;
        }

#pragma unroll
        for (int t = 0; t < 2; ++t)
#pragma unroll
            for (int j = 0; j < 8; ++j) {
                mma_f16(c[t][j], am[t][0], am[t][1], am[t][2], am[t][3],
                        bm[j][0], bm[j][1]);
                mma_f16(c[t][j], ar[t][0], ar[t][1], ar[t][2], ar[t][3],
                        bm[j][0], bm[j][1]);
            }
    }

#pragma unroll
    for (int t = 0; t < 2; ++t) {
        int r0 = m0 + t * 16 + g;
        int r1 = r0 + 8;
        float dv0 = (r0 < N_NODES) ? g_dinv[r0] : 0.f;
        float dv1 = (r1 < N_NODES) ? g_dinv[r1] : 0.f;
#pragma unroll
        for (int j = 0; j < 8; ++j) {
            int col = n0 + j * 8 + tk * 2;
            if (r0 < N_NODES)
                *(__half2*)&g_hh[r0 * 128 + col] =
                    __floats2half2_rn(dv0 * c[t][j][0], dv0 * c[t][j][1]);
            if (r1 < N_NODES)
                *(__half2*)&g_hh[r1 * 128 + col] =
                    __floats2half2_rn(dv1 * c[t][j][2], dv1 * c[t][j][3]);
        }
    }
}

// ---------------------------------------------------------------------------
// Layers 2/3 GEMM: A fp16-exact from permuted g_act, fp16 main-only W.
// ---------------------------------------------------------------------------
template <int LAYER>
__global__ void __launch_bounds__(256)
k_gemm_h() {
    const uint2* Wp = (LAYER == 2) ? g_wpk2 : g_wpk3;
    int tid  = threadIdx.x;
    int warp = tid >> 5, lane = tid & 31;
    int g  = lane >> 2;
    int tk = lane & 3;
    int m0 = blockIdx.x * 128 + (warp & 3) * 32;
    int n0 = (warp >> 2) * 64;

    const uint2* A = (const uint2*)g_act;   // permuted rows: uint2 idx r*32+kc*4+tk

    float c[2][8][4];
#pragma unroll
    for (int t = 0; t < 2; ++t)
#pragma unroll
        for (int j = 0; j < 8; ++j)
#pragma unroll
            for (int q = 0; q < 4; ++q) c[t][j][q] = 0.0f;

#pragma unroll 1
    for (int kc = 0; kc < 8; ++kc) {
        unsigned a[2][4];
#pragma unroll
        for (int t = 0; t < 2; ++t) {
            int r0 = m0 + t * 16 + g;
            int r1 = r0 + 8;
            uint2 z = make_uint2(0u, 0u);
            uint2 v0 = (r0 < N_NODES) ? A[r0 * 32 + kc * 4 + tk] : z;
            uint2 v1 = (r1 < N_NODES) ? A[r1 * 32 + kc * 4 + tk] : z;
            a[t][0] = v0.x; a[t][2] = v0.y;
            a[t][1] = v1.x; a[t][3] = v1.y;
        }

        unsigned bm[8][2];
#pragma unroll
        for (int j = 0; j < 8; ++j) {
            uint2 w = Wp[((kc * 128 + n0 + j * 8 + g) << 2) + tk];
            bm[j][0] = w.x; bm[j][1] = w.y;
        }

#pragma unroll
        for (int t = 0; t < 2; ++t)
#pragma unroll
            for (int j = 0; j < 8; ++j)
                mma_f16(c[t][j], a[t][0], a[t][1], a[t][2], a[t][3],
                        bm[j][0], bm[j][1]);
    }

#pragma unroll
    for (int t = 0; t < 2; ++t) {
        int r0 = m0 + t * 16 + g;
        int r1 = r0 + 8;
        float dv0 = (r0 < N_NODES) ? g_dinv[r0] : 0.f;
        float dv1 = (r1 < N_NODES) ? g_dinv[r1] : 0.f;
#pragma unroll
        for (int j = 0; j < 8; ++j) {
            int col = n0 + j * 8 + tk * 2;
            if (r0 < N_NODES)
                *(__half2*)&g_hh[r0 * 128 + col] =
                    __floats2half2_rn(dv0 * c[t][j][0], dv0 * c[t][j][1]);
            if (r1 < N_NODES)
                *(__half2*)&g_hh[r1 * 128 + col] =
                    __floats2half2_rn(dv1 * c[t][j][2], dv1 * c[t][j][3]);
        }
    }
}

// ---------------------------------------------------------------------------
// Aggregation: FULL WARP per dst node (no divergence), 8 nodes per block.
// out = relu( dinv[dst] * ( sum_src H'[src] + H'[dst] ) + b ).
// TO_OUT=false -> writes g_act in FRAGMENT-PERMUTED order; true -> fp32 OUT.
// ---------------------------------------------------------------------------
template <bool TO_OUT>
__global__ void __launch_bounds__(256)
k_agg(const float* __restrict__ b, float* __restrict__ OUT) {
    int node = blockIdx.x * 8 + (threadIdx.x >> 5);
    int lane = threadIdx.x & 31;
    if (node >= N_NODES) return;

    float acc[8];
    gather_node((const uint4*)g_hh, node, lane, acc);

    if (lane < 16) {
        int l16 = lane;
        float dv = g_dinv[node];
        float4 bb0 = *(const float4*)&b[l16 * 8];
        float4 bb1 = *(const float4*)&b[l16 * 8 + 4];
        float o[8];
        o[0] = fmaxf(fmaf(dv, acc[0], bb0.x), 0.f);
        o[1] = fmaxf(fmaf(dv, acc[1], bb0.y), 0.f);
        o[2] = fmaxf(fmaf(dv, acc[2], bb0.z), 0.f);
        o[3] = fmaxf(fmaf(dv, acc[3], bb0.w), 0.f);
        o[4] = fmaxf(fmaf(dv, acc[4], bb1.x), 0.f);
        o[5] = fmaxf(fmaf(dv, acc[5], bb1.y), 0.f);
        o[6] = fmaxf(fmaf(dv, acc[6], bb1.z), 0.f);
        o[7] = fmaxf(fmaf(dv, acc[7], bb1.w), 0.f);

        if (TO_OUT) {
            ((float4*)OUT)[node * 32 + l16 * 2]     = make_float4(o[0], o[1], o[2], o[3]);
            ((float4*)OUT)[node * 32 + l16 * 2 + 1] = make_float4(o[4], o[5], o[6], o[7]);
        } else {
            int cch = l16 >> 1;
            int odd = l16 & 1;
            unsigned* dst = (unsigned*)g_act + node * 64 + cch * 8 + odd;
            __half2 h0 = __floats2half2_rn(o[0], o[1]);
            __half2 h1 = __floats2half2_rn(o[2], o[3]);
            __half2 h2 = __floats2half2_rn(o[4], o[5]);
            __half2 h3 = __floats2half2_rn(o[6], o[7]);
            dst[0] = *(unsigned*)&h0;
            dst[2] = *(unsigned*)&h1;
            dst[4] = *(unsigned*)&h2;
            dst[6] = *(unsigned*)&h3;
        }
    }
}

// ---------------------------------------------------------------------------
extern "C" void kernel_launch(void* const* d_in, const int* in_sizes, int n_in,
                              void* d_out, int out_size) {
    const float* x  = (const float*)d_in[0];
    const int*   ei = (const int*)d_in[1];
    const float* W1 = (const float*)d_in[2];
    const float* b1 = (const float*)d_in[3];
    const float* W2 = (const float*)d_in[4];
    const float* b2 = (const float*)d_in[5];
    const float* W3 = (const float*)d_in[6];
    const float* b3 = (const float*)d_in[7];
    float* out = (float*)d_out;

    cudaStream_t side = g_res.s;

    // Fork: side stream builds CSR (+dinv early), main does wprep + gemm_l1.
    cudaEventRecord(g_res.fork, 0);
    cudaStreamWaitEvent(side, g_res.fork, 0);

    k_zero_cnt<<<(N_NODES + 255) / 256, 256, 0, side>>>();
    k_count<<<(E_EDGES / 4 + 255) / 256, 256, 0, side>>>(ei);
    k_dinv<<<(N_NODES + 255) / 256, 256, 0, side>>>();
    cudaEventRecord(g_res.dinv, side);
    k_scan_a<<<SCAN_BLOCKS, 1024, 0, side>>>();
    k_scan_b<<<1, 128, 0, side>>>();
    k_scan_c<<<SCAN_BLOCKS, 1024, 0, side>>>();
    k_scatter<<<(E_EDGES / 4 + 255) / 256, 256, 0, side>>>(ei);
    cudaEventRecord(g_res.csr, side);

    const int gemm_blocks = (N_NODES + 127) / 128;          // 782
    const int agg_blocks  = (N_NODES + 7) / 8;              // 12500

    k_wprep_all<<<(3 * 8 * D * 4 + 255) / 256, 256>>>(W1, W2, W3);
    cudaStreamWaitEvent(0, g_res.dinv, 0);
    k_gemm_l1<<<gemm_blocks, 256>>>(x);
    cudaStreamWaitEvent(0, g_res.csr, 0);   // join: agg needs rowptr/csr_src

    // Layer 1: -> g_act (permuted)
    k_agg<false><<<agg_blocks, 256>>>(b1, nullptr);
    // Layer 2
    k_gemm_h<2><<<gemm_blocks, 256>>>();
    k_agg<false><<<agg_blocks, 256>>>(b2, nullptr);
    // Layer 3
    k_gemm_h<3><<<gemm_blocks, 256>>>();
    k_agg<true><<<agg_blocks, 256>>>(b3, out);
}

// round 16
// speedup vs baseline: 1.4509x; 1.0768x over previous
#include <cuda_runtime.h>
#include <cuda_bf16.h>
#include <cuda_fp16.h>

#define N_NODES 100000
#define D 128
#define E_EDGES 1600000
#define SCAN_BLOCKS ((N_NODES + 1023) / 1024)   // 98
#define FULL 0xffffffffu

// Scratch (device globals; no runtime allocation allowed)
__device__ __half g_hh[N_NODES * D];   // pre-normalized messages dinv*H, fp16
__device__ __half g_act[N_NODES * D];  // activations, fp16, FRAGMENT-PERMUTED rows
__device__ float g_dinv[N_NODES];
__device__ int   g_cnt[N_NODES];
__device__ int   g_rowptr[N_NODES + 1];
__device__ int   g_cursor[N_NODES];
__device__ int   g_csr_src[E_EDGES];
__device__ int   g_bsum[SCAN_BLOCKS];
__device__ int   g_boff[SCAN_BLOCKS];
// Fragment-packed W (fp16 main only): [kc][n][tk] -> {bm0,bm1}
__device__ uint2 g_wpk1[8 * D * 4];
__device__ uint2 g_wpk2[8 * D * 4];
__device__ uint2 g_wpk3[8 * D * 4];

// Side stream + events for fork-join graph capture (host driver objects).
struct SideRes {
    cudaStream_t s;
    cudaEvent_t fork, dinv, csr;
    SideRes() {
        cudaStreamCreateWithFlags(&s, cudaStreamNonBlocking);
        cudaEventCreateWithFlags(&fork, cudaEventDisableTiming);
        cudaEventCreateWithFlags(&dinv, cudaEventDisableTiming);
        cudaEventCreateWithFlags(&csr,  cudaEventDisableTiming);
    }
};
static SideRes g_res;

// ---------------------------------------------------------------------------
// Helpers
// ---------------------------------------------------------------------------
__device__ __forceinline__ void split2h(float2 v, unsigned& m, unsigned& r) {
    __half2 hm = __floats2half2_rn(v.x, v.y);
    float2 back = __half22float2(hm);
    __half2 hr = __floats2half2_rn(v.x - back.x, v.y - back.y);
    m = *(unsigned*)&hm;
    r = *(unsigned*)&hr;
}

__device__ __forceinline__ void mma_f16(float* c, unsigned a0, unsigned a1,
                                        unsigned a2, unsigned a3,
                                        unsigned b0, unsigned b1) {
    asm volatile(
        "mma.sync.aligned.m16n8k16.row.col.f32.f16.f16.f32 "
        "{%0,%1,%2,%3}, {%4,%5,%6,%7}, {%8,%9}, {%0,%1,%2,%3};"
        : "+f"(c[0]), "+f"(c[1]), "+f"(c[2]), "+f"(c[3])
        : "r"(a0), "r"(a1), "r"(a2), "r"(a3), "r"(b0), "r"(b1));
}

__device__ __forceinline__ void add_row(float* acc, uint4 raw) {
    float2 q0 = __half22float2(*(__half2*)&raw.x);
    float2 q1 = __half22float2(*(__half2*)&raw.y);
    float2 q2 = __half22float2(*(__half2*)&raw.z);
    float2 q3 = __half22float2(*(__half2*)&raw.w);
    acc[0] += q0.x; acc[1] += q0.y; acc[2] += q1.x; acc[3] += q1.y;
    acc[4] += q2.x; acc[5] += q2.y; acc[6] += q3.x; acc[7] += q3.y;
}

// Full-warp gather for one node: lanes 0-15 handle neighbor stream t+0 (mod 4),
// lanes 16-31 handle stream t+2; each stream consumes TWO neighbors per
// iteration, pairwise-added in fp16 (HADD2) before fp32 accumulation.
// On return, lanes 0-15 hold the combined sum (self + all neighbors) for the
// 16B segment indexed by (lane & 15).
__device__ __forceinline__ void gather_node(const uint4* __restrict__ Hv,
                                            int node, int lane, float* acc) {
    int half = lane >> 4;
    int l16  = lane & 15;

    if (half == 0) {
        uint4 raw = Hv[node * 16 + l16];
        add_row_init:
        {
            float2 q0 = __half22float2(*(__half2*)&raw.x);
            float2 q1 = __half22float2(*(__half2*)&raw.y);
            float2 q2 = __half22float2(*(__half2*)&raw.z);
            float2 q3 = __half22float2(*(__half2*)&raw.w);
            acc[0] = q0.x; acc[1] = q0.y; acc[2] = q1.x; acc[3] = q1.y;
            acc[4] = q2.x; acc[5] = q2.y; acc[6] = q3.x; acc[7] = q3.y;
        }
    } else {
#pragma unroll
        for (int q = 0; q < 8; ++q) acc[q] = 0.0f;
    }

    int j = g_rowptr[node];
    int end = g_rowptr[node + 1];
    while (j < end) {
        int take = end - j;
        if (take > 32) take = 32;
        int sidx = (lane < take) ? g_csr_src[j + lane] : 0;
        // 4 neighbors per warp-iteration: this lane's pair is t+half*2 and
        // t+half*2+1 — two CONSECUTIVE neighbors from its stream.
#pragma unroll 2
        for (int t = 0; t < take; t += 4) {
            int t1 = t + half * 2;
            int t2 = t1 + 1;
            int s1 = __shfl_sync(FULL, sidx, (t1 < take) ? t1 : 0);
            int s2 = __shfl_sync(FULL, sidx, (t2 < take) ? t2 : 0);
            uint4 r1 = make_uint4(0u, 0u, 0u, 0u);
            uint4 r2 = make_uint4(0u, 0u, 0u, 0u);
            if (t1 < take) r1 = Hv[s1 * 16 + l16];
            if (t2 < take) r2 = Hv[s2 * 16 + l16];
            // pairwise fp16 add (zero bits = +0.0h, safe)
            __half2 p0 = __hadd2(*(__half2*)&r1.x, *(__half2*)&r2.x);
            __half2 p1 = __hadd2(*(__half2*)&r1.y, *(__half2*)&r2.y);
            __half2 p2 = __hadd2(*(__half2*)&r1.z, *(__half2*)&r2.z);
            __half2 p3 = __hadd2(*(__half2*)&r1.w, *(__half2*)&r2.w);
            float2 q0 = __half22float2(p0);
            float2 q1 = __half22float2(p1);
            float2 q2 = __half22float2(p2);
            float2 q3 = __half22float2(p3);
            acc[0] += q0.x; acc[1] += q0.y; acc[2] += q1.x; acc[3] += q1.y;
            acc[4] += q2.x; acc[5] += q2.y; acc[6] += q3.x; acc[7] += q3.y;
        }
        j += take;
    }

#pragma unroll
    for (int q = 0; q < 8; ++q)
        acc[q] += __shfl_xor_sync(FULL, acc[q], 16);
}

// ---------------------------------------------------------------------------
// CSR build: histogram -> dinv -> parallel scan -> scatter (4 edges/thread)
// ---------------------------------------------------------------------------
__global__ void k_zero_cnt() {
    int i = blockIdx.x * blockDim.x + threadIdx.x;
    if (i < N_NODES) g_cnt[i] = 0;
}

__global__ void k_count(const int* __restrict__ ei) {
    int e4 = blockIdx.x * blockDim.x + threadIdx.x;
    if (e4 < E_EDGES / 4) {
        int4 d = ((const int4*)(ei + E_EDGES))[e4];
        atomicAdd(&g_cnt[d.x], 1);
        atomicAdd(&g_cnt[d.y], 1);
        atomicAdd(&g_cnt[d.z], 1);
        atomicAdd(&g_cnt[d.w], 1);
    }
}

__global__ void k_dinv() {
    int i = blockIdx.x * blockDim.x + threadIdx.x;
    if (i < N_NODES) g_dinv[i] = rsqrtf((float)g_cnt[i] + 1.0f);
}

__global__ void __launch_bounds__(1024) k_scan_a() {
    __shared__ int sm[1024];
    int t = threadIdx.x;
    int i = blockIdx.x * 1024 + t;
    int v = (i < N_NODES) ? g_cnt[i] : 0;
    sm[t] = v;
    __syncthreads();
#pragma unroll
    for (int off = 1; off < 1024; off <<= 1) {
        int u = (t >= off) ? sm[t - off] : 0;
        __syncthreads();
        sm[t] += u;
        __syncthreads();
    }
    if (i < N_NODES) g_rowptr[i] = sm[t] - v;
    if (t == 1023) g_bsum[blockIdx.x] = sm[1023];
}

__global__ void __launch_bounds__(128) k_scan_b() {
    __shared__ int sm[128];
    int t = threadIdx.x;
    int v = (t < SCAN_BLOCKS) ? g_bsum[t] : 0;
    sm[t] = v;
    __syncthreads();
#pragma unroll
    for (int off = 1; off < 128; off <<= 1) {
        int u = (t >= off) ? sm[t - off] : 0;
        __syncthreads();
        sm[t] += u;
        __syncthreads();
    }
    if (t < SCAN_BLOCKS) g_boff[t] = sm[t] - v;
}

__global__ void __launch_bounds__(1024) k_scan_c() {
    int i = blockIdx.x * 1024 + threadIdx.x;
    if (i < N_NODES) {
        int r = g_rowptr[i] + g_boff[blockIdx.x];
        g_rowptr[i] = r;
        g_cursor[i] = r;
    }
    if (i == 0) g_rowptr[N_NODES] = E_EDGES;
}

__global__ void k_scatter(const int* __restrict__ ei) {
    int e4 = blockIdx.x * blockDim.x + threadIdx.x;
    if (e4 < E_EDGES / 4) {
        int4 s = ((const int4*)ei)[e4];
        int4 d = ((const int4*)(ei + E_EDGES))[e4];
        g_csr_src[atomicAdd(&g_cursor[d.x], 1)] = s.x;
        g_csr_src[atomicAdd(&g_cursor[d.y], 1)] = s.y;
        g_csr_src[atomicAdd(&g_cursor[d.z], 1)] = s.z;
        g_csr_src[atomicAdd(&g_cursor[d.w], 1)] = s.w;
    }
}

// ---------------------------------------------------------------------------
// W prep: fp16 main-only, fragment-packed uint2 {bm0,bm1}, all 3 layers.
// ---------------------------------------------------------------------------
__global__ void k_wprep_all(const float* __restrict__ W1,
                            const float* __restrict__ W2,
                            const float* __restrict__ W3) {
    int t = blockIdx.x * 256 + threadIdx.x;
    if (t >= 3 * 8 * D * 4) return;
    int layer = t / (8 * D * 4);
    int idx   = t % (8 * D * 4);
    int kc = idx >> 9;
    int n  = (idx >> 2) & 127;
    int tk = idx & 3;
    int k0 = kc * 16 + tk * 2;
    int k1 = k0 + 8;

    const float* W = (layer == 0) ? W1 : (layer == 1) ? W2 : W3;
    __half2 m0 = __floats2half2_rn(W[k0 * D + n], W[(k0 + 1) * D + n]);
    __half2 m1 = __floats2half2_rn(W[k1 * D + n], W[(k1 + 1) * D + n]);
    uint2 p = make_uint2(*(unsigned*)&m0, *(unsigned*)&m1);
    if (layer == 0) g_wpk1[idx] = p;
    else if (layer == 1) g_wpk2[idx] = p;
    else g_wpk3[idx] = p;
}

// ---------------------------------------------------------------------------
// Layer-1 GEMM: A = fp16 main+residual of fp32 x (2 MMA terms), W fp16 main.
// 8 warps; warp tile 32x64; block M=128, full N=128. Writes g_hh.
// ---------------------------------------------------------------------------
__global__ void __launch_bounds__(256)
k_gemm_l1(const float* __restrict__ X) {
    int tid  = threadIdx.x;
    int warp = tid >> 5, lane = tid & 31;
    int g  = lane >> 2;
    int tk = lane & 3;
    int m0 = blockIdx.x * 128 + (warp & 3) * 32;
    int n0 = (warp >> 2) * 64;

    float c[2][8][4];
#pragma unroll
    for (int t = 0; t < 2; ++t)
#pragma unroll
        for (int j = 0; j < 8; ++j)
#pragma unroll
            for (int q = 0; q < 4; ++q) c[t][j][q] = 0.0f;

#pragma unroll 1
    for (int kc = 0; kc < 8; ++kc) {
        int kb = kc * 16;

        unsigned am[2][4], ar[2][4];
#pragma unroll
        for (int t = 0; t < 2; ++t) {
            int r0 = m0 + t * 16 + g;
            int r1 = r0 + 8;
            float2 z = make_float2(0.f, 0.f);
            float2 x00 = (r0 < N_NODES) ? *(const float2*)&X[r0 * 128 + kb + tk * 2] : z;
            float2 x10 = (r1 < N_NODES) ? *(const float2*)&X[r1 * 128 + kb + tk * 2] : z;
            float2 x01 = (r0 < N_NODES) ? *(const float2*)&X[r0 * 128 + kb + 8 + tk * 2] : z;
            float2 x11 = (r1 < N_NODES) ? *(const float2*)&X[r1 * 128 + kb + 8 + tk * 2] : z;
            split2h(x00, am[t][0], ar[t][0]);
            split2h(x10, am[t][1], ar[t][1]);
            split2h(x01, am[t][2], ar[t][2]);
            split2h(x11, am[t][3], ar[t][3]);
        }

        unsigned bm[8][2];
#pragma unroll
        for (int j = 0; j < 8; ++j) {
            uint2 w = g_wpk1[((kc * 128 + n0 + j * 8 + g) << 2) + tk];
            bm[j][0] = w.x; bm[j][1] = w.y;
        }

#pragma unroll
        for (int t = 0; t < 2; ++t)
#pragma unroll
            for (int j = 0; j < 8; ++j) {
                mma_f16(c[t][j], am[t][0], am[t][1], am[t][2], am[t][3],
                        bm[j][0], bm[j][1]);
                mma_f16(c[t][j], ar[t][0], ar[t][1], ar[t][2], ar[t][3],
                        bm[j][0], bm[j][1]);
            }
    }

#pragma unroll
    for (int t = 0; t < 2; ++t) {
        int r0 = m0 + t * 16 + g;
        int r1 = r0 + 8;
        float dv0 = (r0 < N_NODES) ? g_dinv[r0] : 0.f;
        float dv1 = (r1 < N_NODES) ? g_dinv[r1] : 0.f;
#pragma unroll
        for (int j = 0; j < 8; ++j) {
            int col = n0 + j * 8 + tk * 2;
            if (r0 < N_NODES)
                *(__half2*)&g_hh[r0 * 128 + col] =
                    __floats2half2_rn(dv0 * c[t][j][0], dv0 * c[t][j][1]);
            if (r1 < N_NODES)
                *(__half2*)&g_hh[r1 * 128 + col] =
                    __floats2half2_rn(dv1 * c[t][j][2], dv1 * c[t][j][3]);
        }
    }
}

// ---------------------------------------------------------------------------
// Layers 2/3 GEMM: A fp16-exact from permuted g_act, fp16 main-only W.
// ---------------------------------------------------------------------------
template <int LAYER>
__global__ void __launch_bounds__(256)
k_gemm_h() {
    const uint2* Wp = (LAYER == 2) ? g_wpk2 : g_wpk3;
    int tid  = threadIdx.x;
    int warp = tid >> 5, lane = tid & 31;
    int g  = lane >> 2;
    int tk = lane & 3;
    int m0 = blockIdx.x * 128 + (warp & 3) * 32;
    int n0 = (warp >> 2) * 64;

    const uint2* A = (const uint2*)g_act;   // permuted rows: uint2 idx r*32+kc*4+tk

    float c[2][8][4];
#pragma unroll
    for (int t = 0; t < 2; ++t)
#pragma unroll
        for (int j = 0; j < 8; ++j)
#pragma unroll
            for (int q = 0; q < 4; ++q) c[t][j][q] = 0.0f;

#pragma unroll 1
    for (int kc = 0; kc < 8; ++kc) {
        unsigned a[2][4];
#pragma unroll
        for (int t = 0; t < 2; ++t) {
            int r0 = m0 + t * 16 + g;
            int r1 = r0 + 8;
            uint2 z = make_uint2(0u, 0u);
            uint2 v0 = (r0 < N_NODES) ? A[r0 * 32 + kc * 4 + tk] : z;
            uint2 v1 = (r1 < N_NODES) ? A[r1 * 32 + kc * 4 + tk] : z;
            a[t][0] = v0.x; a[t][2] = v0.y;
            a[t][1] = v1.x; a[t][3] = v1.y;
        }

        unsigned bm[8][2];
#pragma unroll
        for (int j = 0; j < 8; ++j) {
            uint2 w = Wp[((kc * 128 + n0 + j * 8 + g) << 2) + tk];
            bm[j][0] = w.x; bm[j][1] = w.y;
        }

#pragma unroll
        for (int t = 0; t < 2; ++t)
#pragma unroll
            for (int j = 0; j < 8; ++j)
                mma_f16(c[t][j], a[t][0], a[t][1], a[t][2], a[t][3],
                        bm[j][0], bm[j][1]);
    }

#pragma unroll
    for (int t = 0; t < 2; ++t) {
        int r0 = m0 + t * 16 + g;
        int r1 = r0 + 8;
        float dv0 = (r0 < N_NODES) ? g_dinv[r0] : 0.f;
        float dv1 = (r1 < N_NODES) ? g_dinv[r1] : 0.f;
#pragma unroll
        for (int j = 0; j < 8; ++j) {
            int col = n0 + j * 8 + tk * 2;
            if (r0 < N_NODES)
                *(__half2*)&g_hh[r0 * 128 + col] =
                    __floats2half2_rn(dv0 * c[t][j][0], dv0 * c[t][j][1]);
            if (r1 < N_NODES)
                *(__half2*)&g_hh[r1 * 128 + col] =
                    __floats2half2_rn(dv1 * c[t][j][2], dv1 * c[t][j][3]);
        }
    }
}

// ---------------------------------------------------------------------------
// Aggregation: FULL WARP per dst node (no divergence), 8 nodes per block.
// out = relu( dinv[dst] * ( sum_src H'[src] + H'[dst] ) + b ).
// TO_OUT=false -> writes g_act in FRAGMENT-PERMUTED order; true -> fp32 OUT.
// ---------------------------------------------------------------------------
template <bool TO_OUT>
__global__ void __launch_bounds__(256)
k_agg(const float* __restrict__ b, float* __restrict__ OUT) {
    int node = blockIdx.x * 8 + (threadIdx.x >> 5);
    int lane = threadIdx.x & 31;
    if (node >= N_NODES) return;

    float acc[8];
    gather_node((const uint4*)g_hh, node, lane, acc);

    if (lane < 16) {
        int l16 = lane;
        float dv = g_dinv[node];
        float4 bb0 = *(const float4*)&b[l16 * 8];
        float4 bb1 = *(const float4*)&b[l16 * 8 + 4];
        float o[8];
        o[0] = fmaxf(fmaf(dv, acc[0], bb0.x), 0.f);
        o[1] = fmaxf(fmaf(dv, acc[1], bb0.y), 0.f);
        o[2] = fmaxf(fmaf(dv, acc[2], bb0.z), 0.f);
        o[3] = fmaxf(fmaf(dv, acc[3], bb0.w), 0.f);
        o[4] = fmaxf(fmaf(dv, acc[4], bb1.x), 0.f);
        o[5] = fmaxf(fmaf(dv, acc[5], bb1.y), 0.f);
        o[6] = fmaxf(fmaf(dv, acc[6], bb1.z), 0.f);
        o[7] = fmaxf(fmaf(dv, acc[7], bb1.w), 0.f);

        if (TO_OUT) {
            ((float4*)OUT)[node * 32 + l16 * 2]     = make_float4(o[0], o[1], o[2], o[3]);
            ((float4*)OUT)[node * 32 + l16 * 2 + 1] = make_float4(o[4], o[5], o[6], o[7]);
        } else {
            int cch = l16 >> 1;
            int odd = l16 & 1;
            unsigned* dst = (unsigned*)g_act + node * 64 + cch * 8 + odd;
            __half2 h0 = __floats2half2_rn(o[0], o[1]);
            __half2 h1 = __floats2half2_rn(o[2], o[3]);
            __half2 h2 = __floats2half2_rn(o[4], o[5]);
            __half2 h3 = __floats2half2_rn(o[6], o[7]);
            dst[0] = *(unsigned*)&h0;
            dst[2] = *(unsigned*)&h1;
            dst[4] = *(unsigned*)&h2;
            dst[6] = *(unsigned*)&h3;
        }
    }
}

// ---------------------------------------------------------------------------
extern "C" void kernel_launch(void* const* d_in, const int* in_sizes, int n_in,
                              void* d_out, int out_size) {
    const float* x  = (const float*)d_in[0];
    const int*   ei = (const int*)d_in[1];
    const float* W1 = (const float*)d_in[2];
    const float* b1 = (const float*)d_in[3];
    const float* W2 = (const float*)d_in[4];
    const float* b2 = (const float*)d_in[5];
    const float* W3 = (const float*)d_in[6];
    const float* b3 = (const float*)d_in[7];
    float* out = (float*)d_out;

    cudaStream_t side = g_res.s;

    // Fork: side stream builds CSR (+dinv early), main does wprep + gemm_l1.
    cudaEventRecord(g_res.fork, 0);
    cudaStreamWaitEvent(side, g_res.fork, 0);

    k_zero_cnt<<<(N_NODES + 255) / 256, 256, 0, side>>>();
    k_count<<<(E_EDGES / 4 + 255) / 256, 256, 0, side>>>(ei);
    k_dinv<<<(N_NODES + 255) / 256, 256, 0, side>>>();
    cudaEventRecord(g_res.dinv, side);
    k_scan_a<<<SCAN_BLOCKS, 1024, 0, side>>>();
    k_scan_b<<<1, 128, 0, side>>>();
    k_scan_c<<<SCAN_BLOCKS, 1024, 0, side>>>();
    k_scatter<<<(E_EDGES / 4 + 255) / 256, 256, 0, side>>>(ei);
    cudaEventRecord(g_res.csr, side);

    const int gemm_blocks = (N_NODES + 127) / 128;          // 782
    const int agg_blocks  = (N_NODES + 7) / 8;              // 12500

    k_wprep_all<<<(3 * 8 * D * 4 + 255) / 256, 256>>>(W1, W2, W3);
    cudaStreamWaitEvent(0, g_res.dinv, 0);
    k_gemm_l1<<<gemm_blocks, 256>>>(x);
    cudaStreamWaitEvent(0, g_res.csr, 0);   // join: agg needs rowptr/csr_src

    // Layer 1: -> g_act (permuted)
    k_agg<false><<<agg_blocks, 256>>>(b1, nullptr);
    // Layer 2
    k_gemm_h<2><<<gemm_blocks, 256>>>();
    k_agg<false><<<agg_blocks, 256>>>(b2, nullptr);
    // Layer 3
    k_gemm_h<3><<<gemm_blocks, 256>>>();
    k_agg<true><<<agg_blocks, 256>>>(b3, out);
}

// round 17
// speedup vs baseline: 1.4575x; 1.0045x over previous
#include <cuda_runtime.h>
#include <cuda_bf16.h>
#include <cuda_fp16.h>

#define N_NODES 100000
#define D 128
#define E_EDGES 1600000
#define SCAN_BLOCKS ((N_NODES + 1023) / 1024)   // 98
#define FULL 0xffffffffu

// Scratch (device globals; no runtime allocation allowed)
__device__ __half g_hh[N_NODES * D];   // pre-normalized messages dinv*H, fp16
__device__ __half g_act[N_NODES * D];  // activations, fp16, FRAGMENT-PERMUTED rows
__device__ float g_dinv[N_NODES];
__device__ int   g_cnt[N_NODES];
__device__ int   g_rowptr[N_NODES + 1];
__device__ int   g_cursor[N_NODES];
__device__ int   g_csr_src[E_EDGES];
__device__ int   g_bsum[SCAN_BLOCKS];
__device__ int   g_boff[SCAN_BLOCKS];
// Fragment-packed W (fp16 main only): [kc][n][tk] -> {bm0,bm1}
__device__ uint2 g_wpk1[8 * D * 4];
__device__ uint2 g_wpk2[8 * D * 4];
__device__ uint2 g_wpk3[8 * D * 4];

// Side stream + events for fork-join graph capture (host driver objects).
struct SideRes {
    cudaStream_t s;
    cudaEvent_t fork, dinv, csr;
    SideRes() {
        cudaStreamCreateWithFlags(&s, cudaStreamNonBlocking);
        cudaEventCreateWithFlags(&fork, cudaEventDisableTiming);
        cudaEventCreateWithFlags(&dinv, cudaEventDisableTiming);
        cudaEventCreateWithFlags(&csr,  cudaEventDisableTiming);
    }
};
static SideRes g_res;

// ---------------------------------------------------------------------------
// Helpers
// ---------------------------------------------------------------------------
__device__ __forceinline__ void mma_f16(float* c, unsigned a0, unsigned a1,
                                        unsigned a2, unsigned a3,
                                        unsigned b0, unsigned b1) {
    asm volatile(
        "mma.sync.aligned.m16n8k16.row.col.f32.f16.f16.f32 "
        "{%0,%1,%2,%3}, {%4,%5,%6,%7}, {%8,%9}, {%0,%1,%2,%3};"
        : "+f"(c[0]), "+f"(c[1]), "+f"(c[2]), "+f"(c[3])
        : "r"(a0), "r"(a1), "r"(a2), "r"(a3), "r"(b0), "r"(b1));
}

// Full-warp gather for one node. Lanes 0-15 handle neighbor slots t..t+3,
// lanes 16-31 handle t+4..t+7 (8 neighbors per warp-iteration). Each stream
// pairwise-adds its 4 rows in fp16 (2-level HADD2 tree) before one fp32
// accumulate. On return, lanes 0-15 hold the combined sum (self + all
// neighbors) for the 16B segment indexed by (lane & 15).
__device__ __forceinline__ void gather_node(const uint4* __restrict__ Hv,
                                            int node, int lane, float* acc) {
    int half = lane >> 4;
    int l16  = lane & 15;

    if (half == 0) {
        uint4 raw = Hv[node * 16 + l16];
        float2 q0 = __half22float2(*(__half2*)&raw.x);
        float2 q1 = __half22float2(*(__half2*)&raw.y);
        float2 q2 = __half22float2(*(__half2*)&raw.z);
        float2 q3 = __half22float2(*(__half2*)&raw.w);
        acc[0] = q0.x; acc[1] = q0.y; acc[2] = q1.x; acc[3] = q1.y;
        acc[4] = q2.x; acc[5] = q2.y; acc[6] = q3.x; acc[7] = q3.y;
    } else {
#pragma unroll
        for (int q = 0; q < 8; ++q) acc[q] = 0.0f;
    }

    int j = g_rowptr[node];
    int end = g_rowptr[node + 1];
    while (j < end) {
        int take = end - j;
        if (take > 32) take = 32;
        int sidx = (lane < take) ? g_csr_src[j + lane] : 0;
#pragma unroll 1
        for (int t = 0; t < take; t += 8) {
            int tb = t + half * 4;
            int t0 = tb, t1 = tb + 1, t2 = tb + 2, t3 = tb + 3;
            int s0 = __shfl_sync(FULL, sidx, (t0 < take) ? t0 : 0);
            int s1 = __shfl_sync(FULL, sidx, (t1 < take) ? t1 : 0);
            int s2 = __shfl_sync(FULL, sidx, (t2 < take) ? t2 : 0);
            int s3 = __shfl_sync(FULL, sidx, (t3 < take) ? t3 : 0);
            uint4 r0 = make_uint4(0u, 0u, 0u, 0u);
            uint4 r1 = make_uint4(0u, 0u, 0u, 0u);
            uint4 r2 = make_uint4(0u, 0u, 0u, 0u);
            uint4 r3 = make_uint4(0u, 0u, 0u, 0u);
            if (t0 < take) r0 = Hv[s0 * 16 + l16];
            if (t1 < take) r1 = Hv[s1 * 16 + l16];
            if (t2 < take) r2 = Hv[s2 * 16 + l16];
            if (t3 < take) r3 = Hv[s3 * 16 + l16];
            // 2-level fp16 pairwise tree (zero bits = +0.0h, safe)
            __half2 a0 = __hadd2(__hadd2(*(__half2*)&r0.x, *(__half2*)&r1.x),
                                 __hadd2(*(__half2*)&r2.x, *(__half2*)&r3.x));
            __half2 a1 = __hadd2(__hadd2(*(__half2*)&r0.y, *(__half2*)&r1.y),
                                 __hadd2(*(__half2*)&r2.y, *(__half2*)&r3.y));
            __half2 a2 = __hadd2(__hadd2(*(__half2*)&r0.z, *(__half2*)&r1.z),
                                 __hadd2(*(__half2*)&r2.z, *(__half2*)&r3.z));
            __half2 a3 = __hadd2(__hadd2(*(__half2*)&r0.w, *(__half2*)&r1.w),
                                 __hadd2(*(__half2*)&r2.w, *(__half2*)&r3.w));
            float2 q0 = __half22float2(a0);
            float2 q1 = __half22float2(a1);
            float2 q2 = __half22float2(a2);
            float2 q3 = __half22float2(a3);
            acc[0] += q0.x; acc[1] += q0.y; acc[2] += q1.x; acc[3] += q1.y;
            acc[4] += q2.x; acc[5] += q2.y; acc[6] += q3.x; acc[7] += q3.y;
        }
        j += take;
    }

#pragma unroll
    for (int q = 0; q < 8; ++q)
        acc[q] += __shfl_xor_sync(FULL, acc[q], 16);
}

// ---------------------------------------------------------------------------
// CSR build: histogram -> dinv -> parallel scan -> scatter (4 edges/thread)
// ---------------------------------------------------------------------------
__global__ void k_zero_cnt() {
    int i = blockIdx.x * blockDim.x + threadIdx.x;
    if (i < N_NODES) g_cnt[i] = 0;
}

__global__ void k_count(const int* __restrict__ ei) {
    int e4 = blockIdx.x * blockDim.x + threadIdx.x;
    if (e4 < E_EDGES / 4) {
        int4 d = ((const int4*)(ei + E_EDGES))[e4];
        atomicAdd(&g_cnt[d.x], 1);
        atomicAdd(&g_cnt[d.y], 1);
        atomicAdd(&g_cnt[d.z], 1);
        atomicAdd(&g_cnt[d.w], 1);
    }
}

__global__ void k_dinv() {
    int i = blockIdx.x * blockDim.x + threadIdx.x;
    if (i < N_NODES) g_dinv[i] = rsqrtf((float)g_cnt[i] + 1.0f);
}

__global__ void __launch_bounds__(1024) k_scan_a() {
    __shared__ int sm[1024];
    int t = threadIdx.x;
    int i = blockIdx.x * 1024 + t;
    int v = (i < N_NODES) ? g_cnt[i] : 0;
    sm[t] = v;
    __syncthreads();
#pragma unroll
    for (int off = 1; off < 1024; off <<= 1) {
        int u = (t >= off) ? sm[t - off] : 0;
        __syncthreads();
        sm[t] += u;
        __syncthreads();
    }
    if (i < N_NODES) g_rowptr[i] = sm[t] - v;
    if (t == 1023) g_bsum[blockIdx.x] = sm[1023];
}

__global__ void __launch_bounds__(128) k_scan_b() {
    __shared__ int sm[128];
    int t = threadIdx.x;
    int v = (t < SCAN_BLOCKS) ? g_bsum[t] : 0;
    sm[t] = v;
    __syncthreads();
#pragma unroll
    for (int off = 1; off < 128; off <<= 1) {
        int u = (t >= off) ? sm[t - off] : 0;
        __syncthreads();
        sm[t] += u;
        __syncthreads();
    }
    if (t < SCAN_BLOCKS) g_boff[t] = sm[t] - v;
}

__global__ void __launch_bounds__(1024) k_scan_c() {
    int i = blockIdx.x * 1024 + threadIdx.x;
    if (i < N_NODES) {
        int r = g_rowptr[i] + g_boff[blockIdx.x];
        g_rowptr[i] = r;
        g_cursor[i] = r;
    }
    if (i == 0) g_rowptr[N_NODES] = E_EDGES;
}

__global__ void k_scatter(const int* __restrict__ ei) {
    int e4 = blockIdx.x * blockDim.x + threadIdx.x;
    if (e4 < E_EDGES / 4) {
        int4 s = ((const int4*)ei)[e4];
        int4 d = ((const int4*)(ei + E_EDGES))[e4];
        g_csr_src[atomicAdd(&g_cursor[d.x], 1)] = s.x;
        g_csr_src[atomicAdd(&g_cursor[d.y], 1)] = s.y;
        g_csr_src[atomicAdd(&g_cursor[d.z], 1)] = s.z;
        g_csr_src[atomicAdd(&g_cursor[d.w], 1)] = s.w;
    }
}

// ---------------------------------------------------------------------------
// W prep: fp16 main-only, fragment-packed uint2 {bm0,bm1}, all 3 layers.
// ---------------------------------------------------------------------------
__global__ void k_wprep_all(const float* __restrict__ W1,
                            const float* __restrict__ W2,
                            const float* __restrict__ W3) {
    int t = blockIdx.x * 256 + threadIdx.x;
    if (t >= 3 * 8 * D * 4) return;
    int layer = t / (8 * D * 4);
    int idx   = t % (8 * D * 4);
    int kc = idx >> 9;
    int n  = (idx >> 2) & 127;
    int tk = idx & 3;
    int k0 = kc * 16 + tk * 2;
    int k1 = k0 + 8;

    const float* W = (layer == 0) ? W1 : (layer == 1) ? W2 : W3;
    __half2 m0 = __floats2half2_rn(W[k0 * D + n], W[(k0 + 1) * D + n]);
    __half2 m1 = __floats2half2_rn(W[k1 * D + n], W[(k1 + 1) * D + n]);
    uint2 p = make_uint2(*(unsigned*)&m0, *(unsigned*)&m1);
    if (layer == 0) g_wpk1[idx] = p;
    else if (layer == 1) g_wpk2[idx] = p;
    else g_wpk3[idx] = p;
}

// ---------------------------------------------------------------------------
// Layer-1 GEMM: A = fp16(x) main-only, W fp16 main-only, 1 MMA term.
// 8 warps; warp tile 32x64; block M=128, full N=128. Writes g_hh.
// ---------------------------------------------------------------------------
__global__ void __launch_bounds__(256)
k_gemm_l1(const float* __restrict__ X) {
    int tid  = threadIdx.x;
    int warp = tid >> 5, lane = tid & 31;
    int g  = lane >> 2;
    int tk = lane & 3;
    int m0 = blockIdx.x * 128 + (warp & 3) * 32;
    int n0 = (warp >> 2) * 64;

    float c[2][8][4];
#pragma unroll
    for (int t = 0; t < 2; ++t)
#pragma unroll
        for (int j = 0; j < 8; ++j)
#pragma unroll
            for (int q = 0; q < 4; ++q) c[t][j][q] = 0.0f;

#pragma unroll 1
    for (int kc = 0; kc < 8; ++kc) {
        int kb = kc * 16;

        unsigned a[2][4];
#pragma unroll
        for (int t = 0; t < 2; ++t) {
            int r0 = m0 + t * 16 + g;
            int r1 = r0 + 8;
            float2 z = make_float2(0.f, 0.f);
            float2 x00 = (r0 < N_NODES) ? *(const float2*)&X[r0 * 128 + kb + tk * 2] : z;
            float2 x10 = (r1 < N_NODES) ? *(const float2*)&X[r1 * 128 + kb + tk * 2] : z;
            float2 x01 = (r0 < N_NODES) ? *(const float2*)&X[r0 * 128 + kb + 8 + tk * 2] : z;
            float2 x11 = (r1 < N_NODES) ? *(const float2*)&X[r1 * 128 + kb + 8 + tk * 2] : z;
            __half2 h;
            h = __floats2half2_rn(x00.x, x00.y); a[t][0] = *(unsigned*)&h;
            h = __floats2half2_rn(x10.x, x10.y); a[t][1] = *(unsigned*)&h;
            h = __floats2half2_rn(x01.x, x01.y); a[t][2] = *(unsigned*)&h;
            h = __floats2half2_rn(x11.x, x11.y); a[t][3] = *(unsigned*)&h;
        }

        unsigned bm[8][2];
#pragma unroll
        for (int j = 0; j < 8; ++j) {
            uint2 w = g_wpk1[((kc * 128 + n0 + j * 8 + g) << 2) + tk];
            bm[j][0] = w.x; bm[j][1] = w.y;
        }

#pragma unroll
        for (int t = 0; t < 2; ++t)
#pragma unroll
            for (int j = 0; j < 8; ++j)
                mma_f16(c[t][j], a[t][0], a[t][1], a[t][2], a[t][3],
                        bm[j][0], bm[j][1]);
    }

#pragma unroll
    for (int t = 0; t < 2; ++t) {
        int r0 = m0 + t * 16 + g;
        int r1 = r0 + 8;
        float dv0 = (r0 < N_NODES) ? g_dinv[r0] : 0.f;
        float dv1 = (r1 < N_NODES) ? g_dinv[r1] : 0.f;
#pragma unroll
        for (int j = 0; j < 8; ++j) {
            int col = n0 + j * 8 + tk * 2;
            if (r0 < N_NODES)
                *(__half2*)&g_hh[r0 * 128 + col] =
                    __floats2half2_rn(dv0 * c[t][j][0], dv0 * c[t][j][1]);
            if (r1 < N_NODES)
                *(__half2*)&g_hh[r1 * 128 + col] =
                    __floats2half2_rn(dv1 * c[t][j][2], dv1 * c[t][j][3]);
        }
    }
}

// ---------------------------------------------------------------------------
// Layers 2/3 GEMM: A fp16-exact from permuted g_act, fp16 main-only W.
// ---------------------------------------------------------------------------
template <int LAYER>
__global__ void __launch_bounds__(256)
k_gemm_h() {
    const uint2* Wp = (LAYER == 2) ? g_wpk2 : g_wpk3;
    int tid  = threadIdx.x;
    int warp = tid >> 5, lane = tid & 31;
    int g  = lane >> 2;
    int tk = lane & 3;
    int m0 = blockIdx.x * 128 + (warp & 3) * 32;
    int n0 = (warp >> 2) * 64;

    const uint2* A = (const uint2*)g_act;   // permuted rows: uint2 idx r*32+kc*4+tk

    float c[2][8][4];
#pragma unroll
    for (int t = 0; t < 2; ++t)
#pragma unroll
        for (int j = 0; j < 8; ++j)
#pragma unroll
            for (int q = 0; q < 4; ++q) c[t][j][q] = 0.0f;

#pragma unroll 1
    for (int kc = 0; kc < 8; ++kc) {
        unsigned a[2][4];
#pragma unroll
        for (int t = 0; t < 2; ++t) {
            int r0 = m0 + t * 16 + g;
            int r1 = r0 + 8;
            uint2 z = make_uint2(0u, 0u);
            uint2 v0 = (r0 < N_NODES) ? A[r0 * 32 + kc * 4 + tk] : z;
            uint2 v1 = (r1 < N_NODES) ? A[r1 * 32 + kc * 4 + tk] : z;
            a[t][0] = v0.x; a[t][2] = v0.y;
            a[t][1] = v1.x; a[t][3] = v1.y;
        }

        unsigned bm[8][2];
#pragma unroll
        for (int j = 0; j < 8; ++j) {
            uint2 w = Wp[((kc * 128 + n0 + j * 8 + g) << 2) + tk];
            bm[j][0] = w.x; bm[j][1] = w.y;
        }

#pragma unroll
        for (int t = 0; t < 2; ++t)
#pragma unroll
            for (int j = 0; j < 8; ++j)
                mma_f16(c[t][j], a[t][0], a[t][1], a[t][2], a[t][3],
                        bm[j][0], bm[j][1]);
    }

#pragma unroll
    for (int t = 0; t < 2; ++t) {
        int r0 = m0 + t * 16 + g;
        int r1 = r0 + 8;
        float dv0 = (r0 < N_NODES) ? g_dinv[r0] : 0.f;
        float dv1 = (r1 < N_NODES) ? g_dinv[r1] : 0.f;
#pragma unroll
        for (int j = 0; j < 8; ++j) {
            int col = n0 + j * 8 + tk * 2;
            if (r0 < N_NODES)
                *(__half2*)&g_hh[r0 * 128 + col] =
                    __floats2half2_rn(dv0 * c[t][j][0], dv0 * c[t][j][1]);
            if (r1 < N_NODES)
                *(__half2*)&g_hh[r1 * 128 + col] =
                    __floats2half2_rn(dv1 * c[t][j][2], dv1 * c[t][j][3]);
        }
    }
}

// ---------------------------------------------------------------------------
// Aggregation: FULL WARP per dst node (no divergence), 8 nodes per block.
// out = relu( dinv[dst] * ( sum_src H'[src] + H'[dst] ) + b ).
// TO_OUT=false -> writes g_act in FRAGMENT-PERMUTED order; true -> fp32 OUT.
// ---------------------------------------------------------------------------
template <bool TO_OUT>
__global__ void __launch_bounds__(256)
k_agg(const float* __restrict__ b, float* __restrict__ OUT) {
    int node = blockIdx.x * 8 + (threadIdx.x >> 5);
    int lane = threadIdx.x & 31;
    if (node >= N_NODES) return;

    float acc[8];
    gather_node((const uint4*)g_hh, node, lane, acc);

    if (lane < 16) {
        int l16 = lane;
        float dv = g_dinv[node];
        float4 bb0 = *(const float4*)&b[l16 * 8];
        float4 bb1 = *(const float4*)&b[l16 * 8 + 4];
        float o[8];
        o[0] = fmaxf(fmaf(dv, acc[0], bb0.x), 0.f);
        o[1] = fmaxf(fmaf(dv, acc[1], bb0.y), 0.f);
        o[2] = fmaxf(fmaf(dv, acc[2], bb0.z), 0.f);
        o[3] = fmaxf(fmaf(dv, acc[3], bb0.w), 0.f);
        o[4] = fmaxf(fmaf(dv, acc[4], bb1.x), 0.f);
        o[5] = fmaxf(fmaf(dv, acc[5], bb1.y), 0.f);
        o[6] = fmaxf(fmaf(dv, acc[6], bb1.z), 0.f);
        o[7] = fmaxf(fmaf(dv, acc[7], bb1.w), 0.f);

        if (TO_OUT) {
            ((float4*)OUT)[node * 32 + l16 * 2]     = make_float4(o[0], o[1], o[2], o[3]);
            ((float4*)OUT)[node * 32 + l16 * 2 + 1] = make_float4(o[4], o[5], o[6], o[7]);
        } else {
            int cch = l16 >> 1;
            int odd = l16 & 1;
            unsigned* dst = (unsigned*)g_act + node * 64 + cch * 8 + odd;
            __half2 h0 = __floats2half2_rn(o[0], o[1]);
            __half2 h1 = __floats2half2_rn(o[2], o[3]);
            __half2 h2 = __floats2half2_rn(o[4], o[5]);
            __half2 h3 = __floats2half2_rn(o[6], o[7]);
            dst[0] = *(unsigned*)&h0;
            dst[2] = *(unsigned*)&h1;
            dst[4] = *(unsigned*)&h2;
            dst[6] = *(unsigned*)&h3;
        }
    }
}

// ---------------------------------------------------------------------------
extern "C" void kernel_launch(void* const* d_in, const int* in_sizes, int n_in,
                              void* d_out, int out_size) {
    const float* x  = (const float*)d_in[0];
    const int*   ei = (const int*)d_in[1];
    const float* W1 = (const float*)d_in[2];
    const float* b1 = (const float*)d_in[3];
    const float* W2 = (const float*)d_in[4];
    const float* b2 = (const float*)d_in[5];
    const float* W3 = (const float*)d_in[6];
    const float* b3 = (const float*)d_in[7];
    float* out = (float*)d_out;

    cudaStream_t side = g_res.s;

    // Fork: side stream builds CSR (+dinv early), main does wprep + gemm_l1.
    cudaEventRecord(g_res.fork, 0);
    cudaStreamWaitEvent(side, g_res.fork, 0);

    k_zero_cnt<<<(N_NODES + 255) / 256, 256, 0, side>>>();
    k_count<<<(E_EDGES / 4 + 255) / 256, 256, 0, side>>>(ei);
    k_dinv<<<(N_NODES + 255) / 256, 256, 0, side>>>();
    cudaEventRecord(g_res.dinv, side);
    k_scan_a<<<SCAN_BLOCKS, 1024, 0, side>>>();
    k_scan_b<<<1, 128, 0, side>>>();
    k_scan_c<<<SCAN_BLOCKS, 1024, 0, side>>>();
    k_scatter<<<(E_EDGES / 4 + 255) / 256, 256, 0, side>>>(ei);
    cudaEventRecord(g_res.csr, side);

    const int gemm_blocks = (N_NODES + 127) / 128;          // 782
    const int agg_blocks  = (N_NODES + 7) / 8;              // 12500

    k_wprep_all<<<(3 * 8 * D * 4 + 255) / 256, 256>>>(W1, W2, W3);
    cudaStreamWaitEvent(0, g_res.dinv, 0);
    k_gemm_l1<<<gemm_blocks, 256>>>(x);
    cudaStreamWaitEvent(0, g_res.csr, 0);   // join: agg needs rowptr/csr_src

    // Layer 1: -> g_act (permuted)
    k_agg<false><<<agg_blocks, 256>>>(b1, nullptr);
    // Layer 2
    k_gemm_h<2><<<gemm_blocks, 256>>>();
    k_agg<false><<<agg_blocks, 256>>>(b2, nullptr);
    // Layer 3
    k_gemm_h<3><<<gemm_blocks, 256>>>();
    k_agg<true><<<agg_blocks, 256>>>(b3, out);
}